// round 6
// baseline (speedup 1.0000x reference)
#include <cuda_runtime.h>
#include <cstdint>

#define BATCH    128
#define N0       25600   // 160x160
#define N1       6400    // 80x80
#define N2       1600    // 40x40
#define NTOT     33600
#define KTOP     1000
#define CAND_CAP 4096
#define THREADS  1024
#define WH_BINS  1024    // high-half bins: bin = (key>>21) - 1024
#define WH_STRIDE 34     // u16 row stride (17 words -> conflict-free column sums)

typedef unsigned long long u64;
typedef unsigned int u32;
typedef unsigned short u16;

struct Smem {
    u64 cand[CAND_CAP];          // 32768 B
    u16 wh[WH_BINS][WH_STRIDE];  // 69632 B  per-warp hist, [bin][warp]
    u32 hist[2048];              // 8192 B   reduced histogram (low half normally 0)
    u32 wsum[32];
    u32 wexcl[32];
    int ccount;
    int tbin;
};

__device__ __forceinline__ u32 make_key(u32 u) {
    // order-preserving float->uint transform
    return u ^ (((u32)((int)u >> 31)) | 0x80000000u);
}

__device__ __forceinline__ u64 ce_shfl(u64 v, int j, bool desc, int tid) {
    u64 p = __shfl_xor_sync(0xffffffffu, v, j);
    bool keepmax = (((tid & j) == 0) == desc);
    u64 mx = v > p ? v : p;
    u64 mn = v > p ? p : v;
    return keepmax ? mx : mn;
}

// match_any-aggregated, atomic-free per-warp histogram of one key (hi bins only)
__device__ __forceinline__ void hist_one(Smem& sm, u32 key, int wid, int lane) {
    u32 bin = key >> 21;
    u32 hi = __ballot_sync(0xffffffffu, bin >= 1024u);
    if (bin >= 1024u) {
        u32 mm = __match_any_sync(hi, bin);
        int leader = __ffs(mm) - 1;
        if (lane == leader) {
            u16* cell = &sm.wh[bin - 1024u][wid];
            *cell = (u16)(*cell + (u16)__popc(mm));
        }
    }
}

// Pass A over one source array (padded, warp-uniform trip count)
__device__ __forceinline__ void passA(Smem& sm, const float* src, int n,
                                      int tid, int wid, int lane) {
    const float4* v = reinterpret_cast<const float4*>(src);
    const int n4  = n >> 2;
    const int lim = ((n4 + THREADS - 1) / THREADS) * THREADS;
    for (int i = tid; i < lim; i += THREADS) {
        uint4 kk;
        if (i < n4) {
            float4 f = v[i];
            kk.x = make_key(__float_as_uint(f.x));
            kk.y = make_key(__float_as_uint(f.y));
            kk.z = make_key(__float_as_uint(f.z));
            kk.w = make_key(__float_as_uint(f.w));
        } else {
            kk.x = kk.y = kk.z = kk.w = 0u;  // bin 0 -> skipped by hi filter
        }
        hist_one(sm, kk.x, wid, lane);
        hist_one(sm, kk.y, wid, lane);
        hist_one(sm, kk.z, wid, lane);
        hist_one(sm, kk.w, wid, lane);
    }
}

// Fallback (never taken for Gaussian data): atomic histogram of negative half
__device__ __forceinline__ void passA_neg(Smem& sm, const float* src, int n, int tid) {
    const float4* v = reinterpret_cast<const float4*>(src);
    const int n4 = n >> 2;
    for (int i = tid; i < n4; i += THREADS) {
        float4 f = v[i];
        u32 k0 = make_key(__float_as_uint(f.x));
        u32 k1 = make_key(__float_as_uint(f.y));
        u32 k2 = make_key(__float_as_uint(f.z));
        u32 k3 = make_key(__float_as_uint(f.w));
        if ((k0 >> 21) < 1024u) atomicAdd(&sm.hist[k0 >> 21], 1u);
        if ((k1 >> 21) < 1024u) atomicAdd(&sm.hist[k1 >> 21], 1u);
        if ((k2 >> 21) < 1024u) atomicAdd(&sm.hist[k2 >> 21], 1u);
        if ((k3 >> 21) < 1024u) atomicAdd(&sm.hist[k3 >> 21], 1u);
    }
}

// Pass B: re-read (L2-hot), warp-aggregated compaction of bins >= T
__device__ __forceinline__ void passB(Smem& sm, const float* src, int n, int base,
                                      u32 T, int tid, int lane) {
    const float4* v = reinterpret_cast<const float4*>(src);
    const int n4  = n >> 2;
    const int lim = ((n4 + THREADS - 1) / THREADS) * THREADS;
    for (int i = tid; i < lim; i += THREADS) {
        bool valid = i < n4;
        uint4 kk;
        if (valid) {
            float4 f = v[i];
            kk.x = make_key(__float_as_uint(f.x));
            kk.y = make_key(__float_as_uint(f.y));
            kk.z = make_key(__float_as_uint(f.z));
            kk.w = make_key(__float_as_uint(f.w));
        } else {
            kk.x = kk.y = kk.z = kk.w = 0u;
        }
        #pragma unroll
        for (int s = 0; s < 4; s++) {
            u32 key = (s == 0) ? kk.x : (s == 1) ? kk.y : (s == 2) ? kk.z : kk.w;
            bool pred = valid && ((key >> 21) >= T);
            u32 m = __ballot_sync(0xffffffffu, pred);
            if (m) {
                int bsum = 0;
                if (lane == 0) bsum = atomicAdd(&sm.ccount, __popc(m));
                bsum = __shfl_sync(0xffffffffu, bsum, 0);
                if (pred) {
                    int p = bsum + __popc(m & ((1u << lane) - 1u));
                    if (p < CAND_CAP) {
                        u32 gidx = (u32)(base + 4 * i + s);
                        sm.cand[p] = ((u64)key << 32) | (u32)(~gidx);
                    }
                }
            }
        }
    }
}

__global__ __launch_bounds__(THREADS, 1)
void topk_decode_kernel(const float* __restrict__ cls0,
                        const float* __restrict__ cls1,
                        const float* __restrict__ cls2,
                        const float* __restrict__ bb0,
                        const float* __restrict__ bb1,
                        const float* __restrict__ bb2,
                        float* __restrict__ out)
{
    extern __shared__ char smem_raw[];
    Smem& sm = *reinterpret_cast<Smem*>(smem_raw);
    const int b    = blockIdx.x;
    const int tid  = threadIdx.x;
    const int lane = tid & 31;
    const int wid  = tid >> 5;

    // ---- init ----
    {
        u32* whp = reinterpret_cast<u32*>(&sm.wh[0][0]);
        const int WHW = WH_BINS * WH_STRIDE / 2;  // 17408 u32
        for (int i = tid; i < WHW; i += THREADS) whp[i] = 0u;
        for (int i = tid; i < 2048; i += THREADS) sm.hist[i] = 0u;
        if (tid == 0) { sm.ccount = 0; sm.tbin = -1; }
    }
    __syncthreads();

    const float* c0 = cls0 + (size_t)b * N0;
    const float* c1 = cls1 + (size_t)b * N1;
    const float* c2 = cls2 + (size_t)b * N2;

    // ---- pass A: stream logits, atomic-free per-warp histogram (hi half) ----
    passA(sm, c0, N0, tid, wid, lane);
    passA(sm, c1, N1, tid, wid, lane);
    passA(sm, c2, N2, tid, wid, lane);
    __syncthreads();

    // ---- reduce per-warp hists: thread t sums bin t's 32 u16 counters ----
    {
        const u32* row = reinterpret_cast<const u32*>(&sm.wh[tid][0]);
        u32 acc = 0;
        #pragma unroll
        for (int j = 0; j < 16; j++) acc += row[j];   // packed halves, no carry (<=33600)
        sm.hist[1024 + tid] = (acc & 0xFFFFu) + (acc >> 16);
    }
    __syncthreads();

    // ---- suffix scan over 2048 bins (2 per thread) -> threshold bin ----
    for (int attempt = 0; attempt < 2; attempt++) {
        u32 h0 = sm.hist[2 * tid], h1 = sm.hist[2 * tid + 1];
        u32 s2 = h0 + h1;
        u32 v = s2;
        #pragma unroll
        for (int off = 1; off < 32; off <<= 1) {
            u32 u = __shfl_down_sync(0xffffffffu, v, off);
            if (lane + off < 32) v += u;
        }
        if (lane == 0) sm.wsum[wid] = v;
        __syncthreads();
        if (tid < 32) {
            u32 t = sm.wsum[tid];
            u32 w = t;
            #pragma unroll
            for (int off = 1; off < 32; off <<= 1) {
                u32 u = __shfl_down_sync(0xffffffffu, w, off);
                if (tid + off < 32) w += u;
            }
            sm.wexcl[tid] = w - t;
        }
        __syncthreads();
        u32 gsuf  = v + sm.wexcl[wid];
        u32 gnext = gsuf - s2;
        if (gsuf >= (u32)KTOP && gnext < (u32)KTOP) {
            sm.tbin = (gnext + h1 >= (u32)KTOP) ? (2 * tid + 1) : (2 * tid);
        }
        __syncthreads();
        if (sm.tbin >= 0) break;
        // fallback: positives insufficient -> histogram negative half (rare)
        if (attempt == 0) {
            passA_neg(sm, c0, N0, tid);
            passA_neg(sm, c1, N1, tid);
            passA_neg(sm, c2, N2, tid);
            __syncthreads();
        }
    }
    const u32 T = (u32)sm.tbin;

    // ---- pass B: compaction from L2-hot global ----
    passB(sm, c0, N0, 0,       T, tid, lane);
    passB(sm, c1, N1, N0,      T, tid, lane);
    passB(sm, c2, N2, N0 + N1, T, tid, lane);
    __syncthreads();

    int M = sm.ccount; if (M > CAND_CAP) M = CAND_CAP;
    const bool fastP = (M <= 2048);
    const int  P     = fastP ? 2048 : 4096;
    for (int i = M + tid; i < P; i += THREADS) sm.cand[i] = 0ull;
    __syncthreads();

    u64 a;
    if (fastP) {
        // ---- hybrid reg/shfl + smem bitonic sort, P=2048 desc ----
        a = sm.cand[tid];
        u64 bb = sm.cand[tid + 1024];

        #pragma unroll
        for (int k = 2; k <= 32; k <<= 1) {
            #pragma unroll
            for (int j = k >> 1; j >= 1; j >>= 1) {
                bool dA = ((tid & k) == 0);
                a  = ce_shfl(a,  j, dA, tid);
                bb = ce_shfl(bb, j, dA, tid);
            }
        }
        sm.cand[tid] = a;
        sm.cand[tid + 1024] = bb;
        __syncthreads();

        for (int k = 64; k <= 2048; k <<= 1) {
            for (int j = k >> 1; j >= 32; j >>= 1) {
                int i   = ((tid & ~(j - 1)) << 1) | (tid & (j - 1));
                int ixj = i | j;
                bool desc = ((i & k) == 0);
                u64 x = sm.cand[i];
                u64 y = sm.cand[ixj];
                bool sw = desc ? (x < y) : (x > y);
                if (sw) { sm.cand[i] = y; sm.cand[ixj] = x; }
                __syncthreads();
            }
            a  = sm.cand[tid];
            bb = sm.cand[tid + 1024];
            bool dA = ((tid & k) == 0);
            bool dB = (((tid + 1024) & k) == 0);
            #pragma unroll
            for (int j = 16; j >= 1; j >>= 1) {
                a  = ce_shfl(a,  j, dA, tid);
                bb = ce_shfl(bb, j, dB, tid);
            }
            if (k < 2048) {
                sm.cand[tid] = a;
                sm.cand[tid + 1024] = bb;
                __syncthreads();
            }
        }
        // rank tid lives in register `a`
    } else {
        // ---- generic smem bitonic, P=4096 (rare fallback) ----
        for (int k = 2; k <= 4096; k <<= 1) {
            for (int j = k >> 1; j > 0; j >>= 1) {
                for (int i = tid; i < 4096; i += THREADS) {
                    int ixj = i ^ j;
                    if (ixj > i) {
                        u64 x = sm.cand[i];
                        u64 y = sm.cand[ixj];
                        bool desc = ((i & k) == 0);
                        if (desc ? (x < y) : (x > y)) {
                            sm.cand[i] = y;
                            sm.cand[ixj] = x;
                        }
                    }
                }
                __syncthreads();
            }
        }
        a = sm.cand[tid];
    }

    // ---- emit top-K ----
    float* out_boxes  = out;                            // [B, K, 4]
    float* out_scores = out + (size_t)BATCH * KTOP * 4; // [B, K, 1]

    if (tid < KTOP) {
        u64 e = a;
        u32 key = (u32)(e >> 32);
        u32 idx = ~(u32)(e & 0xFFFFFFFFull);

        float logit = (key & 0x80000000u)
                    ? __uint_as_float(key ^ 0x80000000u)
                    : __uint_as_float(~key);
        float sc = 1.0f / (1.0f + expf(-logit));
        out_scores[(size_t)b * KTOP + tid] = sc;

        int jj, w, st, hw;
        const float* bp;
        if (idx < N0)           { jj = (int)idx;            w = 160; st = 8;  hw = N0; bp = bb0 + (size_t)b * 4 * N0; }
        else if (idx < N0 + N1) { jj = (int)idx - N0;       w = 80;  st = 16; hw = N1; bp = bb1 + (size_t)b * 4 * N1; }
        else                    { jj = (int)idx - N0 - N1;  w = 40;  st = 32; hw = N2; bp = bb2 + (size_t)b * 4 * N2; }

        int y = jj / w;
        int x = jj - y * w;
        float px = (float)(x * st);
        float py = (float)(y * st);

        float dl = bp[jj];
        float dt = bp[hw + jj];
        float dr = bp[2 * hw + jj];
        float db = bp[3 * hw + jj];

        float4 box = make_float4(px - dl, py - dt, px + dr, py + db);
        *reinterpret_cast<float4*>(&out_boxes[((size_t)b * KTOP + tid) * 4]) = box;
    }
}

extern "C" void kernel_launch(void* const* d_in, const int* in_sizes, int n_in,
                              void* d_out, int out_size)
{
    const float *cls0, *cls1, *cls2, *b0, *b1, *b2;

    const int S_CLS0 = BATCH * N0;      // 3276800
    const int S_BB0  = BATCH * 4 * N0;  // 13107200

    if (n_in >= 6 && in_sizes[0] == S_CLS0 && in_sizes[1] == S_BB0) {
        // dict-insertion order: cls0, bbox0, cls1, bbox1, cls2, bbox2
        cls0 = (const float*)d_in[0]; b0 = (const float*)d_in[1];
        cls1 = (const float*)d_in[2]; b1 = (const float*)d_in[3];
        cls2 = (const float*)d_in[4]; b2 = (const float*)d_in[5];
    } else if (n_in >= 6 && in_sizes[0] == S_BB0) {
        // alphabetical order: bbox0, bbox1, bbox2, cls0, cls1, cls2
        b0   = (const float*)d_in[0]; b1   = (const float*)d_in[1];
        b2   = (const float*)d_in[2]; cls0 = (const float*)d_in[3];
        cls1 = (const float*)d_in[4]; cls2 = (const float*)d_in[5];
    } else {
        // signature order: cls0, cls1, cls2, bbox0, bbox1, bbox2
        cls0 = (const float*)d_in[0]; cls1 = (const float*)d_in[1];
        cls2 = (const float*)d_in[2]; b0   = (const float*)d_in[3];
        b1   = (const float*)d_in[4]; b2   = (const float*)d_in[5];
    }
    (void)in_sizes; (void)out_size;

    cudaFuncSetAttribute(topk_decode_kernel,
                         cudaFuncAttributeMaxDynamicSharedMemorySize,
                         (int)sizeof(Smem));

    topk_decode_kernel<<<BATCH, THREADS, sizeof(Smem)>>>(
        cls0, cls1, cls2, b0, b1, b2, (float*)d_out);
}

// round 7
// speedup vs baseline: 1.5388x; 1.5388x over previous
#include <cuda_runtime.h>
#include <cstdint>

#define BATCH    128
#define N0       25600   // 160x160
#define N1       6400    // 80x80
#define N2       1600    // 40x40
#define NTOT     33600
#define KTOP     1000
#define CAND_CAP 4096
#define THREADS  1024
#define THR_F    1.7f    // conservative cutoff; exact fallback if bracket fails

typedef unsigned long long u64;
typedef unsigned int u32;

struct Smem {
    u64 cand[CAND_CAP];     // 32768 B
    u32 hist[2048];         // 8192 B  (fallback only)
    u32 wsum[32];
    u32 wexcl[32];
    int ccount;
    int tbin;
};

__device__ __forceinline__ u32 make_key(u32 u) {
    // order-preserving float->uint transform
    return u ^ (((u32)((int)u >> 31)) | 0x80000000u);
}

__device__ __forceinline__ u64 ce_shfl(u64 v, int j, bool desc, int tid) {
    u64 p = __shfl_xor_sync(0xffffffffu, v, j);
    bool keepmax = (((tid & j) == 0) == desc);
    u64 mx = v > p ? v : p;
    u64 mn = v > p ? p : v;
    return keepmax ? mx : mn;
}

// Streaming threshold-compaction: push (key, ~idx) for every f > THR_F.
__device__ __forceinline__ void compact_thr(Smem& sm, const float* src, int n,
                                            int base, int tid, int lane) {
    const float4* v = reinterpret_cast<const float4*>(src);
    const int n4  = n >> 2;
    const int lim = ((n4 + THREADS - 1) / THREADS) * THREADS;
    for (int i = tid; i < lim; i += THREADS) {
        bool valid = i < n4;
        float4 f = make_float4(-1e30f, -1e30f, -1e30f, -1e30f);
        if (valid) f = v[i];
        #pragma unroll
        for (int s = 0; s < 4; s++) {
            float x = (s == 0) ? f.x : (s == 1) ? f.y : (s == 2) ? f.z : f.w;
            bool pred = valid && (x > THR_F);
            u32 m = __ballot_sync(0xffffffffu, pred);
            if (m) {
                int bsum = 0;
                if (lane == 0) bsum = atomicAdd(&sm.ccount, __popc(m));
                bsum = __shfl_sync(0xffffffffu, bsum, 0);
                if (pred) {
                    int p = bsum + __popc(m & ((1u << lane) - 1u));
                    if (p < CAND_CAP) {
                        u32 gidx = (u32)(base + 4 * i + s);
                        sm.cand[p] = ((u64)make_key(__float_as_uint(x)) << 32) |
                                     (u32)(~gidx);
                    }
                }
            }
        }
    }
}

// ---------- exact fallback (never taken on in-distribution data) ----------
__device__ __forceinline__ void hist_pass(Smem& sm, const float* src, int n, int tid) {
    const float4* v = reinterpret_cast<const float4*>(src);
    const int n4 = n >> 2;
    for (int i = tid; i < n4; i += THREADS) {
        float4 f = v[i];
        atomicAdd(&sm.hist[make_key(__float_as_uint(f.x)) >> 21], 1u);
        atomicAdd(&sm.hist[make_key(__float_as_uint(f.y)) >> 21], 1u);
        atomicAdd(&sm.hist[make_key(__float_as_uint(f.z)) >> 21], 1u);
        atomicAdd(&sm.hist[make_key(__float_as_uint(f.w)) >> 21], 1u);
    }
}

__device__ __forceinline__ void compact_bin(Smem& sm, const float* src, int n,
                                            int base, u32 T, int tid, int lane) {
    const float4* v = reinterpret_cast<const float4*>(src);
    const int n4  = n >> 2;
    const int lim = ((n4 + THREADS - 1) / THREADS) * THREADS;
    for (int i = tid; i < lim; i += THREADS) {
        bool valid = i < n4;
        float4 f = make_float4(0, 0, 0, 0);
        if (valid) f = v[i];
        #pragma unroll
        for (int s = 0; s < 4; s++) {
            float x = (s == 0) ? f.x : (s == 1) ? f.y : (s == 2) ? f.z : f.w;
            u32 key = make_key(__float_as_uint(x));
            bool pred = valid && ((key >> 21) >= T);
            u32 m = __ballot_sync(0xffffffffu, pred);
            if (m) {
                int bsum = 0;
                if (lane == 0) bsum = atomicAdd(&sm.ccount, __popc(m));
                bsum = __shfl_sync(0xffffffffu, bsum, 0);
                if (pred) {
                    int p = bsum + __popc(m & ((1u << lane) - 1u));
                    if (p < CAND_CAP) {
                        u32 gidx = (u32)(base + 4 * i + s);
                        sm.cand[p] = ((u64)key << 32) | (u32)(~gidx);
                    }
                }
            }
        }
    }
}
// --------------------------------------------------------------------------

__global__ __launch_bounds__(THREADS, 1)
void topk_decode_kernel(const float* __restrict__ cls0,
                        const float* __restrict__ cls1,
                        const float* __restrict__ cls2,
                        const float* __restrict__ bb0,
                        const float* __restrict__ bb1,
                        const float* __restrict__ bb2,
                        float* __restrict__ out)
{
    extern __shared__ char smem_raw[];
    Smem& sm = *reinterpret_cast<Smem*>(smem_raw);
    const int b    = blockIdx.x;
    const int tid  = threadIdx.x;
    const int lane = tid & 31;
    const int wid  = tid >> 5;

    if (tid == 0) { sm.ccount = 0; sm.tbin = -1; }
    __syncthreads();

    const float* c0 = cls0 + (size_t)b * N0;
    const float* c1 = cls1 + (size_t)b * N1;
    const float* c2 = cls2 + (size_t)b * N2;

    // ---- single streaming pass: threshold compaction, no histogram ----
    compact_thr(sm, c0, N0, 0,       tid, lane);
    compact_thr(sm, c1, N1, N0,      tid, lane);
    compact_thr(sm, c2, N2, N0 + N1, tid, lane);
    __syncthreads();

    int M = sm.ccount;

    // ---- exact fallback if the fixed threshold failed to bracket K ----
    if (M < KTOP || M > CAND_CAP) {
        for (int i = tid; i < 2048; i += THREADS) sm.hist[i] = 0u;
        if (tid == 0) sm.ccount = 0;
        __syncthreads();

        hist_pass(sm, c0, N0, tid);
        hist_pass(sm, c1, N1, tid);
        hist_pass(sm, c2, N2, tid);
        __syncthreads();

        // suffix scan over 2048 bins (2/thread) -> threshold bin
        u32 h0 = sm.hist[2 * tid], h1 = sm.hist[2 * tid + 1];
        u32 s2 = h0 + h1;
        u32 v = s2;
        #pragma unroll
        for (int off = 1; off < 32; off <<= 1) {
            u32 u = __shfl_down_sync(0xffffffffu, v, off);
            if (lane + off < 32) v += u;
        }
        if (lane == 0) sm.wsum[wid] = v;
        __syncthreads();
        if (tid < 32) {
            u32 t = sm.wsum[tid];
            u32 w = t;
            #pragma unroll
            for (int off = 1; off < 32; off <<= 1) {
                u32 u = __shfl_down_sync(0xffffffffu, w, off);
                if (tid + off < 32) w += u;
            }
            sm.wexcl[tid] = w - t;
        }
        __syncthreads();
        u32 gsuf  = v + sm.wexcl[wid];
        u32 gnext = gsuf - s2;
        if (gsuf >= (u32)KTOP && gnext < (u32)KTOP)
            sm.tbin = (gnext + h1 >= (u32)KTOP) ? (2 * tid + 1) : (2 * tid);
        __syncthreads();

        u32 T = (u32)sm.tbin;
        compact_bin(sm, c0, N0, 0,       T, tid, lane);
        compact_bin(sm, c1, N1, N0,      T, tid, lane);
        compact_bin(sm, c2, N2, N0 + N1, T, tid, lane);
        __syncthreads();
        M = sm.ccount;
        if (M > CAND_CAP) M = CAND_CAP;
    }

    const bool fastP = (M <= 2048);
    const int  P     = fastP ? 2048 : 4096;
    for (int i = M + tid; i < P; i += THREADS) sm.cand[i] = 0ull;
    __syncthreads();

    u64 a;
    if (fastP) {
        // ---- hybrid reg/shfl + smem bitonic sort, P=2048 desc ----
        a = sm.cand[tid];
        u64 bb = sm.cand[tid + 1024];

        #pragma unroll
        for (int k = 2; k <= 32; k <<= 1) {
            #pragma unroll
            for (int j = k >> 1; j >= 1; j >>= 1) {
                bool dA = ((tid & k) == 0);
                a  = ce_shfl(a,  j, dA, tid);
                bb = ce_shfl(bb, j, dA, tid);
            }
        }
        sm.cand[tid] = a;
        sm.cand[tid + 1024] = bb;
        __syncthreads();

        for (int k = 64; k <= 2048; k <<= 1) {
            for (int j = k >> 1; j >= 32; j >>= 1) {
                int i   = ((tid & ~(j - 1)) << 1) | (tid & (j - 1));
                int ixj = i | j;
                bool desc = ((i & k) == 0);
                u64 x = sm.cand[i];
                u64 y = sm.cand[ixj];
                bool sw = desc ? (x < y) : (x > y);
                if (sw) { sm.cand[i] = y; sm.cand[ixj] = x; }
                __syncthreads();
            }
            a  = sm.cand[tid];
            bb = sm.cand[tid + 1024];
            bool dA = ((tid & k) == 0);
            bool dB = (((tid + 1024) & k) == 0);
            #pragma unroll
            for (int j = 16; j >= 1; j >>= 1) {
                a  = ce_shfl(a,  j, dA, tid);
                bb = ce_shfl(bb, j, dB, tid);
            }
            if (k < 2048) {
                sm.cand[tid] = a;
                sm.cand[tid + 1024] = bb;
                __syncthreads();
            }
        }
        // rank tid lives in register `a`
    } else {
        // ---- generic smem bitonic, P=4096 (rare) ----
        for (int k = 2; k <= 4096; k <<= 1) {
            for (int j = k >> 1; j > 0; j >>= 1) {
                for (int i = tid; i < 4096; i += THREADS) {
                    int ixj = i ^ j;
                    if (ixj > i) {
                        u64 x = sm.cand[i];
                        u64 y = sm.cand[ixj];
                        bool desc = ((i & k) == 0);
                        if (desc ? (x < y) : (x > y)) {
                            sm.cand[i] = y;
                            sm.cand[ixj] = x;
                        }
                    }
                }
                __syncthreads();
            }
        }
        a = sm.cand[tid];
    }

    // ---- emit top-K ----
    float* out_boxes  = out;                            // [B, K, 4]
    float* out_scores = out + (size_t)BATCH * KTOP * 4; // [B, K, 1]

    if (tid < KTOP) {
        u64 e = a;
        u32 key = (u32)(e >> 32);
        u32 idx = ~(u32)(e & 0xFFFFFFFFull);

        float logit = (key & 0x80000000u)
                    ? __uint_as_float(key ^ 0x80000000u)
                    : __uint_as_float(~key);
        float sc = 1.0f / (1.0f + expf(-logit));
        out_scores[(size_t)b * KTOP + tid] = sc;

        int jj, w, st, hw;
        const float* bp;
        if (idx < N0)           { jj = (int)idx;            w = 160; st = 8;  hw = N0; bp = bb0 + (size_t)b * 4 * N0; }
        else if (idx < N0 + N1) { jj = (int)idx - N0;       w = 80;  st = 16; hw = N1; bp = bb1 + (size_t)b * 4 * N1; }
        else                    { jj = (int)idx - N0 - N1;  w = 40;  st = 32; hw = N2; bp = bb2 + (size_t)b * 4 * N2; }

        int y = jj / w;
        int x = jj - y * w;
        float px = (float)(x * st);
        float py = (float)(y * st);

        float dl = bp[jj];
        float dt = bp[hw + jj];
        float dr = bp[2 * hw + jj];
        float db = bp[3 * hw + jj];

        float4 box = make_float4(px - dl, py - dt, px + dr, py + db);
        *reinterpret_cast<float4*>(&out_boxes[((size_t)b * KTOP + tid) * 4]) = box;
    }
}

extern "C" void kernel_launch(void* const* d_in, const int* in_sizes, int n_in,
                              void* d_out, int out_size)
{
    const float *cls0, *cls1, *cls2, *b0, *b1, *b2;

    const int S_CLS0 = BATCH * N0;      // 3276800
    const int S_BB0  = BATCH * 4 * N0;  // 13107200

    if (n_in >= 6 && in_sizes[0] == S_CLS0 && in_sizes[1] == S_BB0) {
        // dict-insertion order: cls0, bbox0, cls1, bbox1, cls2, bbox2
        cls0 = (const float*)d_in[0]; b0 = (const float*)d_in[1];
        cls1 = (const float*)d_in[2]; b1 = (const float*)d_in[3];
        cls2 = (const float*)d_in[4]; b2 = (const float*)d_in[5];
    } else if (n_in >= 6 && in_sizes[0] == S_BB0) {
        // alphabetical order: bbox0, bbox1, bbox2, cls0, cls1, cls2
        b0   = (const float*)d_in[0]; b1   = (const float*)d_in[1];
        b2   = (const float*)d_in[2]; cls0 = (const float*)d_in[3];
        cls1 = (const float*)d_in[4]; cls2 = (const float*)d_in[5];
    } else {
        // signature order: cls0, cls1, cls2, bbox0, bbox1, bbox2
        cls0 = (const float*)d_in[0]; cls1 = (const float*)d_in[1];
        cls2 = (const float*)d_in[2]; b0   = (const float*)d_in[3];
        b1   = (const float*)d_in[4]; b2   = (const float*)d_in[5];
    }
    (void)in_sizes; (void)out_size;

    cudaFuncSetAttribute(topk_decode_kernel,
                         cudaFuncAttributeMaxDynamicSharedMemorySize,
                         (int)sizeof(Smem));

    topk_decode_kernel<<<BATCH, THREADS, sizeof(Smem)>>>(
        cls0, cls1, cls2, b0, b1, b2, (float*)d_out);
}